// round 8
// baseline (speedup 1.0000x reference)
#include <cuda_runtime.h>
#include <cuda_fp16.h>
#include <cstdint>

// dw[s,t] = SCALE * sum_b nt[b,s] * ap[b,t]
// SCALE = (0.05*0.05 - 0.01*0.05) * 0.001 / 256 = 7.8125e-9
#define S_DIM 8192
#define T_DIM 8192
#define K_DIM 256

static constexpr float SCALE_F = 7.8125e-9f;

static constexpr int THREADS = 256;
static constexpr int TILE_M  = 256;
static constexpr int TILE_N  = 128;
static constexpr int KC      = 64;            // K rows per stage
static constexpr int NCHUNK  = K_DIM / KC;    // 4 (all prefetched)

// smem: [k][m] for A (m=256 contig, padded), [k][n] for B (n=128 contig, padded)
static constexpr int A_PITCHB  = (TILE_M + 8) * 2;   // 528 B  (132 words -> 4r banks, conflict-free)
static constexpr int B_PITCHB  = (TILE_N + 8) * 2;   // 272 B  (68 words  -> 4r banks, conflict-free)
static constexpr int STAGE_A   = KC * A_PITCHB;      // 33792
static constexpr int STAGE_B   = KC * B_PITCHB;      // 17408
static constexpr int STAGE_TOT = STAGE_A + STAGE_B;  // 51200
static constexpr int SMEM_BYTES = NCHUNK * STAGE_TOT; // 204800 (fits 227KB)

// fp16 copies of the two inputs (static device scratch; no runtime alloc)
__device__ __half g_nth[(size_t)K_DIM * S_DIM];
__device__ __half g_aph[(size_t)K_DIM * T_DIM];

// ---------------- convert pass: fp32 -> fp16 ----------------
__global__ void cvt_kernel(const float* __restrict__ a, const float* __restrict__ b) {
    const int N4 = K_DIM * S_DIM / 4;
    int i = blockIdx.x * blockDim.x + threadIdx.x;
    const float4* src;
    __half2* dst;
    int j;
    if (i < N4)          { src = (const float4*)a; dst = (__half2*)g_nth; j = i; }
    else if (i < 2 * N4) { src = (const float4*)b; dst = (__half2*)g_aph; j = i - N4; }
    else return;
    float4 v = src[j];
    dst[2 * j]     = __floats2half2_rn(v.x, v.y);
    dst[2 * j + 1] = __floats2half2_rn(v.z, v.w);
}

// ---------------- helpers ----------------
__device__ __forceinline__ uint32_t smem_u32(const void* p) {
    uint32_t a;
    asm("{ .reg .u64 t; cvta.to.shared.u64 t, %1; cvt.u32.u64 %0, t; }" : "=r"(a) : "l"(p));
    return a;
}

__device__ __forceinline__ void cp16(uint32_t s, const void* g) {
    asm volatile("cp.async.cg.shared.global [%0], [%1], 16;" :: "r"(s), "l"(g));
}

template <int N>
__device__ __forceinline__ void cp_wait() {
    asm volatile("cp.async.wait_group %0;" :: "n"(N) : "memory");
}

__device__ __forceinline__ void ldmx4t(uint32_t* d, uint32_t addr) {
    asm volatile("ldmatrix.sync.aligned.m8n8.x4.trans.shared.b16 {%0,%1,%2,%3}, [%4];"
                 : "=r"(d[0]), "=r"(d[1]), "=r"(d[2]), "=r"(d[3]) : "r"(addr));
}

__device__ __forceinline__ void mma16816(float* d, const uint32_t* a, uint32_t b0, uint32_t b1) {
    asm volatile(
        "mma.sync.aligned.m16n8k16.row.col.f32.f16.f16.f32 "
        "{%0,%1,%2,%3}, {%4,%5,%6,%7}, {%8,%9}, {%0,%1,%2,%3};"
        : "+f"(d[0]), "+f"(d[1]), "+f"(d[2]), "+f"(d[3])
        : "r"(a[0]), "r"(a[1]), "r"(a[2]), "r"(a[3]), "r"(b0), "r"(b1));
}

// ---------------- GEMM: out[8192,8192] = SCALE * A^T(256x8192) B(256x8192) ----------------
__global__ __launch_bounds__(THREADS, 1)
void stdp_gemm_kernel(float* __restrict__ out) {
    extern __shared__ __align__(16) char smem[];
    const uint32_t sb = smem_u32(smem);
    const int tid = threadIdx.x;
    const int bm = blockIdx.x;   // M tile (32, fast dim -> wave shares B tiles in L2)
    const int bn = blockIdx.y;   // N tile (64)

    const __half* __restrict__ A = g_nth;  // [k][m], m contiguous
    const __half* __restrict__ B = g_aph;  // [k][n], n contiguous

    const size_t a_g0 = (size_t)bm * TILE_M;
    const size_t b_g0 = (size_t)bn * TILE_N;

    // ---- prologue: prefetch ALL four K-stages (one commit group each) ----
#pragma unroll
    for (int st = 0; st < NCHUNK; st++) {
        const int k0 = st * KC;
        const uint32_t sa = sb + (uint32_t)st * STAGE_TOT;
        const uint32_t sbB = sa + STAGE_A;
        // A: 64 rows x 32 segs of 16B -> 2048 chunks, 8 per thread
#pragma unroll
        for (int i = 0; i < 8; i++) {
            int c = tid + i * THREADS;
            int row = c >> 5, seg = c & 31;
            cp16(sa + (uint32_t)(row * A_PITCHB + seg * 16),
                 A + (size_t)(k0 + row) * S_DIM + a_g0 + seg * 8);
        }
        // B: 64 rows x 16 segs -> 1024 chunks, 4 per thread
#pragma unroll
        for (int i = 0; i < 4; i++) {
            int c = tid + i * THREADS;
            int row = c >> 4, seg = c & 15;
            cp16(sbB + (uint32_t)(row * B_PITCHB + seg * 16),
                 B + (size_t)(k0 + row) * T_DIM + b_g0 + seg * 8);
        }
        asm volatile("cp.async.commit_group;" ::: "memory");
    }

    // ---- warp layout: 8 warps = 4(m) x 2(n); warp tile 64x64 ----
    const int warp = tid >> 5, lane = tid & 31;
    const int wm = warp & 3;       // m offset wm*64
    const int wn = warp >> 2;      // n offset wn*64
    const int tile = lane >> 3, r = lane & 7;

    // A frag addr (x4.trans): reg order (m0-7,k0-7)(m8-15,k0-7)(m0-7,k8-15)(m8-15,k8-15)
    const uint32_t a_off = (uint32_t)(((tile >> 1) * 8 + r) * A_PITCHB + (tile & 1) * 16 + wm * 64 * 2);
    // B frag addr (x4.trans): reg order (n0-7,k0-7)(n0-7,k8-15)(n8-15,k0-7)(n8-15,k8-15)
    const uint32_t b_off = (uint32_t)STAGE_A +
        (uint32_t)(((tile & 1) * 8 + r) * B_PITCHB + (tile >> 1) * 16 + wn * 64 * 2);

    float acc[4][8][4];
#pragma unroll
    for (int mi = 0; mi < 4; mi++)
#pragma unroll
        for (int nj = 0; nj < 8; nj++)
#pragma unroll
            for (int q = 0; q < 4; q++) acc[mi][nj][q] = 0.f;

    // ---- mainloop: 4 stages, no loads inside — just wait for prefetched data ----
#pragma unroll 1
    for (int c = 0; c < NCHUNK; c++) {
        switch (c) {
            case 0: cp_wait<3>(); break;
            case 1: cp_wait<2>(); break;
            case 2: cp_wait<1>(); break;
            default: cp_wait<0>(); break;
        }
        __syncthreads();
        const uint32_t stbase = sb + (uint32_t)c * STAGE_TOT;
#pragma unroll
        for (int ks = 0; ks < KC / 16; ks++) {
            const uint32_t ka = stbase + (uint32_t)(ks * 16 * A_PITCHB) + a_off;
            const uint32_t kb = stbase + (uint32_t)(ks * 16 * B_PITCHB) + b_off;
            uint32_t af[4][4], bf[4][4];
#pragma unroll
            for (int mi = 0; mi < 4; mi++) ldmx4t(af[mi], ka + mi * 32);
#pragma unroll
            for (int nb = 0; nb < 4; nb++) ldmx4t(bf[nb], kb + nb * 32);
#pragma unroll
            for (int mi = 0; mi < 4; mi++)
#pragma unroll
                for (int nj = 0; nj < 8; nj++)
                    mma16816(acc[mi][nj], af[mi],
                             bf[nj >> 1][(nj & 1) * 2], bf[nj >> 1][(nj & 1) * 2 + 1]);
        }
    }

    // ---- epilogue: scale + fp32 stores ----
    const int gr = lane >> 2, cq = lane & 3;
    const size_t row0 = (size_t)bm * TILE_M + wm * 64 + gr;
    const int col0 = bn * TILE_N + wn * 64 + cq * 2;
#pragma unroll
    for (int mi = 0; mi < 4; mi++) {
#pragma unroll
        for (int nj = 0; nj < 8; nj++) {
            float2 v0 = make_float2(acc[mi][nj][0] * SCALE_F, acc[mi][nj][1] * SCALE_F);
            float2 v1 = make_float2(acc[mi][nj][2] * SCALE_F, acc[mi][nj][3] * SCALE_F);
            *(float2*)(out + (row0 + mi * 16) * T_DIM + col0 + nj * 8) = v0;
            *(float2*)(out + (row0 + mi * 16 + 8) * T_DIM + col0 + nj * 8) = v1;
        }
    }
}

extern "C" void kernel_launch(void* const* d_in, const int* in_sizes, int n_in,
                              void* d_out, int out_size) {
    const float* nt = (const float*)d_in[0];  // neurotransmitters (256, 8192)
    const float* ap = (const float*)d_in[2];  // action_potential  (256, 8192)
    float* out = (float*)d_out;               // (8192, 8192) fp32

    cvt_kernel<<<(2 * K_DIM * S_DIM / 4 + 255) / 256, 256>>>(nt, ap);

    cudaFuncSetAttribute(stdp_gemm_kernel,
                         cudaFuncAttributeMaxDynamicSharedMemorySize, SMEM_BYTES);
    dim3 grid(S_DIM / TILE_M, T_DIM / TILE_N);  // (32, 64)
    stdp_gemm_kernel<<<grid, THREADS, SMEM_BYTES>>>(out);
}

// round 9
// speedup vs baseline: 1.0772x; 1.0772x over previous
#include <cuda_runtime.h>
#include <cuda_fp16.h>
#include <cstdint>

// dw[s,t] = SCALE * sum_b nt[b,s] * ap[b,t]
// SCALE = (0.05*0.05 - 0.01*0.05) * 0.001 / 256 = 7.8125e-9
#define S_DIM 8192
#define T_DIM 8192
#define K_DIM 256

static constexpr float SCALE_F = 7.8125e-9f;

static constexpr int THREADS = 256;
static constexpr int KC      = 64;           // K rows per chunk
static constexpr int NCHUNK  = K_DIM / KC;   // 4 chunks per tile
static constexpr int NTM     = S_DIM / 128;  // 64 M tiles
static constexpr int NTN     = T_DIM / 128;  // 64 N tiles
static constexpr int NTILES  = NTM * NTN;    // 4096
static constexpr int GRID    = 304;          // 2 CTAs/SM x 152 SMs (persistent)

static constexpr int PITCH     = 136;            // smem row pitch in halves
static constexpr int PITCHB    = PITCH * 2;      // 272 B (68 words -> conflict-free ldmatrix)
static constexpr int STAGE_OP  = KC * PITCHB;    // 17408 B per operand per stage
static constexpr int STAGE_TOT = 2 * STAGE_OP;   // 34816
static constexpr int NSTAGE    = 3;
static constexpr int SMEM_BYTES = NSTAGE * STAGE_TOT;  // 104448 -> 2 CTAs/SM

// fp16 copies of the two inputs (static device scratch; no runtime alloc)
__device__ __half g_nth[(size_t)K_DIM * S_DIM];
__device__ __half g_aph[(size_t)K_DIM * T_DIM];

// ---------------- convert pass: fp32 -> fp16 ----------------
__global__ void cvt_kernel(const float* __restrict__ a, const float* __restrict__ b) {
    const int N4 = K_DIM * S_DIM / 4;
    int i = blockIdx.x * blockDim.x + threadIdx.x;
    const float4* src;
    __half2* dst;
    int j;
    if (i < N4)          { src = (const float4*)a; dst = (__half2*)g_nth; j = i; }
    else if (i < 2 * N4) { src = (const float4*)b; dst = (__half2*)g_aph; j = i - N4; }
    else return;
    float4 v = src[j];
    dst[2 * j]     = __floats2half2_rn(v.x, v.y);
    dst[2 * j + 1] = __floats2half2_rn(v.z, v.w);
}

// ---------------- helpers ----------------
__device__ __forceinline__ uint32_t smem_u32(const void* p) {
    uint32_t a;
    asm("{ .reg .u64 t; cvta.to.shared.u64 t, %1; cvt.u32.u64 %0, t; }" : "=r"(a) : "l"(p));
    return a;
}

__device__ __forceinline__ void cp16(uint32_t s, const void* g) {
    asm volatile("cp.async.cg.shared.global [%0], [%1], 16;" :: "r"(s), "l"(g));
}

__device__ __forceinline__ void ldmx4t(uint32_t* d, uint32_t addr) {
    asm volatile("ldmatrix.sync.aligned.m8n8.x4.trans.shared.b16 {%0,%1,%2,%3}, [%4];"
                 : "=r"(d[0]), "=r"(d[1]), "=r"(d[2]), "=r"(d[3]) : "r"(addr));
}

__device__ __forceinline__ void mma16816(float* d, const uint32_t* a, uint32_t b0, uint32_t b1) {
    asm volatile(
        "mma.sync.aligned.m16n8k16.row.col.f32.f16.f16.f32 "
        "{%0,%1,%2,%3}, {%4,%5,%6,%7}, {%8,%9}, {%0,%1,%2,%3};"
        : "+f"(d[0]), "+f"(d[1]), "+f"(d[2]), "+f"(d[3])
        : "r"(a[0]), "r"(a[1]), "r"(a[2]), "r"(a[3]), "r"(b0), "r"(b1));
}

// ---------------- persistent GEMM: out = SCALE * A^T(256x8192) B(256x8192) ----------------
__global__ __launch_bounds__(THREADS, 2)
void stdp_gemm_kernel(float* __restrict__ out) {
    extern __shared__ __align__(16) char smem[];
    const uint32_t sb = smem_u32(smem);
    const int tid = threadIdx.x;
    const int bid = blockIdx.x;

    const __half* __restrict__ A = g_nth;  // [k][m], m contiguous
    const __half* __restrict__ B = g_aph;  // [k][n], n contiguous

    // per-thread cp.async assignment: 4 (row,seg) chunks per operand per stage
    int rowv[4], segv[4];
#pragma unroll
    for (int i = 0; i < 4; i++) {
        int cc = tid + i * THREADS;
        rowv[i] = cc >> 4;
        segv[i] = cc & 15;
    }

    // Issue the loads for local chunk index gc (this CTA's stream), or an
    // empty commit group if past the end (keeps wait_group accounting aligned).
#define ISSUE(gc)                                                                  \
    do {                                                                           \
        int _t = (gc) >> 2;                                                        \
        int _tile = bid + _t * GRID;                                               \
        if (_tile < NTILES) {                                                      \
            int _bm = _tile & (NTM - 1);                                           \
            int _bn = _tile >> 6;                                                  \
            int _k0 = ((gc) & 3) * KC;                                             \
            uint32_t _sbase = sb + (uint32_t)((gc) % NSTAGE) * STAGE_TOT;          \
            _Pragma("unroll")                                                      \
            for (int i = 0; i < 4; i++) {                                          \
                uint32_t _so = (uint32_t)(rowv[i] * PITCHB + segv[i] * 16);        \
                cp16(_sbase + _so,                                                 \
                     A + (size_t)(_k0 + rowv[i]) * S_DIM + _bm * 128 + segv[i] * 8); \
                cp16(_sbase + STAGE_OP + _so,                                      \
                     B + (size_t)(_k0 + rowv[i]) * T_DIM + _bn * 128 + segv[i] * 8); \
            }                                                                      \
        }                                                                          \
        asm volatile("cp.async.commit_group;" ::: "memory");                       \
    } while (0)

    const int warp = tid >> 5, lane = tid & 31;
    const int wm = warp & 1;        // m offset wm*64
    const int wn = warp >> 1;       // n offset wn*32
    const int tile4 = lane >> 3, r = lane & 7;

    // ldmatrix.x4.trans lane offsets (bytes within stage)
    const uint32_t a_off = (uint32_t)((((tile4 >> 1) * 8 + r) * PITCHB) + (tile4 & 1) * 16 + wm * 64 * 2);
    const uint32_t b_off = (uint32_t)((((tile4 & 1) * 8 + r) * PITCHB) + (tile4 >> 1) * 16 + wn * 32 * 2)
                           + (uint32_t)STAGE_OP;

    // prime the pipeline with the first two chunks of this CTA's first tile
    ISSUE(0);
    ISSUE(1);

    int lc = 0;  // local compute-chunk counter (continuous across tiles)

    for (int t = 0;; t++) {
        const int tile = bid + t * GRID;
        if (tile >= NTILES) break;
        const int bm = tile & (NTM - 1);
        const int bn = tile >> 6;

        float acc[4][4][4];
#pragma unroll
        for (int mi = 0; mi < 4; mi++)
#pragma unroll
            for (int nj = 0; nj < 4; nj++)
#pragma unroll
                for (int q = 0; q < 4; q++) acc[mi][nj][q] = 0.f;

#pragma unroll 1
        for (int j = 0; j < NCHUNK; j++) {
            asm volatile("cp.async.wait_group 1;" ::: "memory");
            __syncthreads();
            ISSUE(lc + 2);  // may belong to the NEXT tile -> cross-tile overlap

            const uint32_t stbase = sb + (uint32_t)(lc % NSTAGE) * STAGE_TOT;
#pragma unroll
            for (int ks = 0; ks < KC / 16; ks++) {
                const uint32_t ka = stbase + (uint32_t)(ks * 16 * PITCHB) + a_off;
                const uint32_t kb = stbase + (uint32_t)(ks * 16 * PITCHB) + b_off;
                uint32_t af[4][4], bf[2][4];
#pragma unroll
                for (int mi = 0; mi < 4; mi++) ldmx4t(af[mi], ka + mi * 32);
#pragma unroll
                for (int nb = 0; nb < 2; nb++) ldmx4t(bf[nb], kb + nb * 32);
#pragma unroll
                for (int mi = 0; mi < 4; mi++)
#pragma unroll
                    for (int nj = 0; nj < 4; nj++)
                        mma16816(acc[mi][nj], af[mi],
                                 bf[nj >> 1][(nj & 1) * 2], bf[nj >> 1][(nj & 1) * 2 + 1]);
            }
            lc++;
        }

        // epilogue overlaps with the in-flight cp.async of the next tile
        const int gr = lane >> 2, cq = lane & 3;
        const size_t row0 = (size_t)bm * 128 + wm * 64 + gr;
        const int col0 = bn * 128 + wn * 32 + cq * 2;
#pragma unroll
        for (int mi = 0; mi < 4; mi++) {
#pragma unroll
            for (int nj = 0; nj < 4; nj++) {
                float2 v0 = make_float2(acc[mi][nj][0] * SCALE_F, acc[mi][nj][1] * SCALE_F);
                float2 v1 = make_float2(acc[mi][nj][2] * SCALE_F, acc[mi][nj][3] * SCALE_F);
                *(float2*)(out + (row0 + mi * 16) * T_DIM + col0 + nj * 8) = v0;
                *(float2*)(out + (row0 + mi * 16 + 8) * T_DIM + col0 + nj * 8) = v1;
            }
        }
    }
#undef ISSUE
}

extern "C" void kernel_launch(void* const* d_in, const int* in_sizes, int n_in,
                              void* d_out, int out_size) {
    const float* nt = (const float*)d_in[0];  // neurotransmitters (256, 8192)
    const float* ap = (const float*)d_in[2];  // action_potential  (256, 8192)
    float* out = (float*)d_out;               // (8192, 8192) fp32

    cvt_kernel<<<(2 * K_DIM * S_DIM / 4 + 255) / 256, 256>>>(nt, ap);

    cudaFuncSetAttribute(stdp_gemm_kernel,
                         cudaFuncAttributeMaxDynamicSharedMemorySize, SMEM_BYTES);
    stdp_gemm_kernel<<<GRID, THREADS, SMEM_BYTES>>>(out);
}

// round 12
// speedup vs baseline: 1.1795x; 1.0949x over previous
#include <cuda_runtime.h>
#include <cuda_fp16.h>
#include <cstdint>

// dw[s,t] = SCALE * sum_b nt[b,s] * ap[b,t]
// SCALE = (0.05*0.05 - 0.01*0.05) * 0.001 / 256 = 7.8125e-9
#define S_DIM 8192
#define T_DIM 8192
#define K_DIM 256

static constexpr float SCALE_F = 7.8125e-9f;

static constexpr int THREADS = 128;            // 4 warps, warp tile 64x64
static constexpr int KC      = 64;             // K rows per stage
static constexpr int NCHUNK  = K_DIM / KC;     // 4
static constexpr int PITCH     = 136;          // smem row pitch in halves
static constexpr int PITCHB    = PITCH * 2;    // 272 B (68 words -> conflict-free ldmatrix)
static constexpr int STAGE_OP  = KC * PITCHB;  // 17408 B per operand per stage
static constexpr int STAGE_TOT = 2 * STAGE_OP; // 34816
static constexpr int NSTAGE    = 3;
static constexpr int SMEM_BYTES = NSTAGE * STAGE_TOT;  // 104448 -> 2 CTAs/SM

// fp16 copies of the two inputs (static device scratch; no runtime alloc)
__device__ __half g_nth[(size_t)K_DIM * S_DIM];
__device__ __half g_aph[(size_t)K_DIM * T_DIM];

// ---------------- convert pass: fp32 -> fp16 ----------------
__global__ void cvt_kernel(const float* __restrict__ a, const float* __restrict__ b) {
    const int N4 = K_DIM * S_DIM / 4;
    int i = blockIdx.x * blockDim.x + threadIdx.x;
    const float4* src;
    __half2* dst;
    int j;
    if (i < N4)          { src = (const float4*)a; dst = (__half2*)g_nth; j = i; }
    else if (i < 2 * N4) { src = (const float4*)b; dst = (__half2*)g_aph; j = i - N4; }
    else return;
    float4 v = src[j];
    dst[2 * j]     = __floats2half2_rn(v.x, v.y);
    dst[2 * j + 1] = __floats2half2_rn(v.z, v.w);
}

// ---------------- helpers ----------------
__device__ __forceinline__ uint32_t smem_u32(const void* p) {
    uint32_t a;
    asm("{ .reg .u64 t; cvta.to.shared.u64 t, %1; cvt.u32.u64 %0, t; }" : "=r"(a) : "l"(p));
    return a;
}

__device__ __forceinline__ void cp16(uint32_t s, const void* g) {
    asm volatile("cp.async.cg.shared.global [%0], [%1], 16;" :: "r"(s), "l"(g));
}

__device__ __forceinline__ void ldmx4t(uint32_t* d, uint32_t addr) {
    asm volatile("ldmatrix.sync.aligned.m8n8.x4.trans.shared.b16 {%0,%1,%2,%3}, [%4];"
                 : "=r"(d[0]), "=r"(d[1]), "=r"(d[2]), "=r"(d[3]) : "r"(addr));
}

__device__ __forceinline__ void mma16816(float* d, const uint32_t* a, uint32_t b0, uint32_t b1) {
    asm volatile(
        "mma.sync.aligned.m16n8k16.row.col.f32.f16.f16.f32 "
        "{%0,%1,%2,%3}, {%4,%5,%6,%7}, {%8,%9}, {%0,%1,%2,%3};"
        : "+f"(d[0]), "+f"(d[1]), "+f"(d[2]), "+f"(d[3])
        : "r"(a[0]), "r"(a[1]), "r"(a[2]), "r"(a[3]), "r"(b0), "r"(b1));
}

// ---------------- GEMM: out[8192,8192] = SCALE * A^T(256x8192) B(256x8192) ----------------
__global__ __launch_bounds__(THREADS, 2)
void stdp_gemm_kernel(float* __restrict__ out) {
    extern __shared__ __align__(16) char smem[];
    const uint32_t sb = smem_u32(smem);
    const int tid = threadIdx.x;
    const int bm = blockIdx.x;   // M tile (64, fast dim -> wave shares B tiles in L2)
    const int bn = blockIdx.y;   // N tile (64)

    const __half* __restrict__ A = g_nth;  // [k][m], m contiguous
    const __half* __restrict__ B = g_aph;  // [k][n], n contiguous

    const size_t a_g0 = (size_t)bm * 128;
    const size_t b_g0 = (size_t)bn * 128;

    // cp.async mapping: 8 (row,seg) 16B chunks per operand per thread per stage
    int rowv[8], segv[8];
#pragma unroll
    for (int i = 0; i < 8; i++) {
        int cc = tid + i * THREADS;
        rowv[i] = cc >> 4;
        segv[i] = cc & 15;
    }

#define LOAD_STAGE(st, k0)                                                          \
    do {                                                                            \
        uint32_t _sbase = sb + (uint32_t)(st) * STAGE_TOT;                          \
        _Pragma("unroll")                                                           \
        for (int i = 0; i < 8; i++) {                                               \
            uint32_t _so = (uint32_t)(rowv[i] * PITCHB + segv[i] * 16);             \
            cp16(_sbase + _so,                                                      \
                 A + (size_t)((k0) + rowv[i]) * S_DIM + a_g0 + segv[i] * 8);        \
            cp16(_sbase + STAGE_OP + _so,                                           \
                 B + (size_t)((k0) + rowv[i]) * T_DIM + b_g0 + segv[i] * 8);        \
        }                                                                           \
    } while (0)

    LOAD_STAGE(0, 0);
    asm volatile("cp.async.commit_group;" ::: "memory");
    LOAD_STAGE(1, KC);
    asm volatile("cp.async.commit_group;" ::: "memory");

    // ---- warp layout: 4 warps = 2(m) x 2(n); warp tile 64x64 ----
    const int warp = tid >> 5, lane = tid & 31;
    const int wm = warp & 1;        // m offset wm*64
    const int wn = warp >> 1;       // n offset wn*64
    const int t4 = lane >> 3, r = lane & 7;

    // A frag (x4.trans): (m0-7,k0-7)(m8-15,k0-7)(m0-7,k8-15)(m8-15,k8-15)
    const uint32_t a_off = (uint32_t)(((t4 >> 1) * 8 + r) * PITCHB + (t4 & 1) * 16 + wm * 64 * 2);
    // B frag (x4.trans): (n0-7,k0-7)(n0-7,k8-15)(n8-15,k0-7)(n8-15,k8-15)
    const uint32_t b_off = (uint32_t)STAGE_OP +
        (uint32_t)(((t4 & 1) * 8 + r) * PITCHB + (t4 >> 1) * 16 + wn * 64 * 2);

    float acc[4][8][4];
#pragma unroll
    for (int mi = 0; mi < 4; mi++)
#pragma unroll
        for (int nj = 0; nj < 8; nj++)
#pragma unroll
            for (int q = 0; q < 4; q++) acc[mi][nj][q] = 0.f;

    uint32_t af[2][4][4], bf[2][4][4];   // double-buffered fragments

#pragma unroll 1
    for (int c = 0; c < NCHUNK; c++) {
        asm volatile("cp.async.wait_group 1;" ::: "memory");
        __syncthreads();
        if (c + 2 < NCHUNK) LOAD_STAGE(c + 2 < NSTAGE ? c + 2 : c + 2 - NSTAGE, (c + 2) * KC);
        asm volatile("cp.async.commit_group;" ::: "memory");

        const int st = (c < NSTAGE) ? c : c - NSTAGE;
        const uint32_t stbase = sb + (uint32_t)st * STAGE_TOT;

        // prefetch ks=0 fragments
#pragma unroll
        for (int mi = 0; mi < 4; mi++) ldmx4t(af[0][mi], stbase + a_off + mi * 32);
#pragma unroll
        for (int nb = 0; nb < 4; nb++) ldmx4t(bf[0][nb], stbase + b_off + nb * 32);

#pragma unroll
        for (int ks = 0; ks < KC / 16; ks++) {
            const int cur = ks & 1, nxt = cur ^ 1;
            if (ks < KC / 16 - 1) {
                const uint32_t ka = stbase + (uint32_t)((ks + 1) * 16 * PITCHB);
#pragma unroll
                for (int mi = 0; mi < 4; mi++) ldmx4t(af[nxt][mi], ka + a_off + mi * 32);
#pragma unroll
                for (int nb = 0; nb < 4; nb++) ldmx4t(bf[nxt][nb], ka + b_off + nb * 32);
            }
#pragma unroll
            for (int mi = 0; mi < 4; mi++)
#pragma unroll
                for (int nj = 0; nj < 8; nj++)
                    mma16816(acc[mi][nj], af[cur][mi],
                             bf[cur][nj >> 1][(nj & 1) * 2], bf[cur][nj >> 1][(nj & 1) * 2 + 1]);
        }
    }

    // ---- epilogue: scale + fp32 stores ----
    const int gr = lane >> 2, cq = lane & 3;
    const size_t row0 = (size_t)bm * 128 + wm * 64 + gr;
    const int col0 = bn * 128 + wn * 64 + cq * 2;
#pragma unroll
    for (int mi = 0; mi < 4; mi++) {
#pragma unroll
        for (int nj = 0; nj < 8; nj++) {
            float2 v0 = make_float2(acc[mi][nj][0] * SCALE_F, acc[mi][nj][1] * SCALE_F);
            float2 v1 = make_float2(acc[mi][nj][2] * SCALE_F, acc[mi][nj][3] * SCALE_F);
            *(float2*)(out + (row0 + mi * 16) * T_DIM + col0 + nj * 8) = v0;
            *(float2*)(out + (row0 + mi * 16 + 8) * T_DIM + col0 + nj * 8) = v1;
        }
    }
#undef LOAD_STAGE
}

extern "C" void kernel_launch(void* const* d_in, const int* in_sizes, int n_in,
                              void* d_out, int out_size) {
    const float* nt = (const float*)d_in[0];  // neurotransmitters (256, 8192)
    const float* ap = (const float*)d_in[2];  // action_potential  (256, 8192)
    float* out = (float*)d_out;               // (8192, 8192) fp32

    cvt_kernel<<<(2 * K_DIM * S_DIM / 4 + 255) / 256, 256>>>(nt, ap);

    cudaFuncSetAttribute(stdp_gemm_kernel,
                         cudaFuncAttributeMaxDynamicSharedMemorySize, SMEM_BYTES);
    dim3 grid(S_DIM / 128, T_DIM / 128);  // (64, 64)
    stdp_gemm_kernel<<<grid, THREADS, SMEM_BYTES>>>(out);
}